// round 5
// baseline (speedup 1.0000x reference)
#include <cuda_runtime.h>
#include <cuda_bf16.h>

// HistogramLoss: loss = mean |hist(fake) - hist(real)| over [B,C,BINS] rows,
// histograms per-(b,c)-row normalized. Every clipped element lands in a bin,
// so each row sums to exactly H*W -> normalization is a constant scale and
// all counting stays integer (bit-deterministic, stateless across replays).

#define ROWS 96               // B*C = 32*3
#define BINS 64
#define NTHREADS 256
#define EPB 65536             // elements per block (256 per thread, fits u16)
#define MAXCHUNKS 4           // hw / EPB = 262144 / 65536

// Per-block partials: [tensor(2)][row(96)][bin(64)][chunk(4)] u32.
// Every launch fully overwrites its slots -> no zeroing kernel, no state.
__device__ uint4 g_part4[2 * ROWS * BINS];   // one uint4 = 4 chunk partials

__global__ __launch_bounds__(NTHREADS)
void hist_kernel(const float* __restrict__ fake,
                 const float* __restrict__ real,
                 int hw, int chunks) {
    // Per-thread privatized u16 counters, packed so bin-pair (2r,2r+1) for
    // thread t shares one 32-bit word:
    //   byte addr = ((bin & 62) << 9) + (t << 2) + ((bin & 1) << 1)
    // -> bank = t & 31 : strictly lane-dependent, ZERO conflicts for any data.
    __shared__ unsigned char s_raw[32 * NTHREADS * 4];   // 32 KB

    const int t = threadIdx.x;
    const int row = blockIdx.x / chunks;
    const int chunk = blockIdx.x - row * chunks;
    const int tensor = blockIdx.y;
    const float* __restrict__ src = tensor ? real : fake;

    // Zero the table (uint4 stores)
    uint4* sz = reinterpret_cast<uint4*>(s_raw);
    #pragma unroll
    for (int i = t; i < (32 * NTHREADS * 4) / 16; i += NTHREADS)
        sz[i] = make_uint4(0u, 0u, 0u, 0u);
    __syncthreads();

    const float4* __restrict__ p = reinterpret_cast<const float4*>(
        src + (size_t)row * (size_t)hw + (size_t)chunk * EPB);
    const int n4 = EPB / 4;                 // 16384
    const int t4 = t << 2;

    #pragma unroll 4
    for (int i = t; i < n4; i += NTHREADS) {
        float4 v = p[i];
        // torch.histc over [0,1]: clip, *BINS, trunc, clamp top bin.
        int b0 = min((int)(fminf(fmaxf(v.x, 0.0f), 1.0f) * 64.0f), 63);
        int b1 = min((int)(fminf(fmaxf(v.y, 0.0f), 1.0f) * 64.0f), 63);
        int b2 = min((int)(fminf(fmaxf(v.z, 0.0f), 1.0f) * 64.0f), 63);
        int b3 = min((int)(fminf(fmaxf(v.w, 0.0f), 1.0f) * 64.0f), 63);
        unsigned short* c0 = (unsigned short*)(s_raw + (((b0 & 62) << 9) + t4 + ((b0 & 1) << 1)));
        unsigned short* c1 = (unsigned short*)(s_raw + (((b1 & 62) << 9) + t4 + ((b1 & 1) << 1)));
        unsigned short* c2 = (unsigned short*)(s_raw + (((b2 & 62) << 9) + t4 + ((b2 & 1) << 1)));
        unsigned short* c3 = (unsigned short*)(s_raw + (((b3 & 62) << 9) + t4 + ((b3 & 1) << 1)));
        *c0 += 1; *c1 += 1; *c2 += 1; *c3 += 1;
    }
    __syncthreads();

    // Reduce 256 private copies -> 64 bins. Word-row r holds bins (2r, 2r+1):
    // lo half = bin 2r, hi half = bin 2r+1. 8 warps x 4 word-rows each.
    const unsigned int* sw = reinterpret_cast<const unsigned int*>(s_raw);
    const int warp = t >> 5;
    const int lane = t & 31;
    unsigned int* gp = reinterpret_cast<unsigned int*>(g_part4);
    const int pbase = ((tensor * ROWS + row) * BINS) * MAXCHUNKS + chunk;

    #pragma unroll
    for (int r = warp; r < 32; r += NTHREADS / 32) {
        unsigned int lo = 0, hi = 0;
        #pragma unroll
        for (int j = 0; j < NTHREADS / 32; ++j) {
            unsigned int w = sw[(r << 8) + lane + (j << 5)];
            lo += w & 0xFFFFu;
            hi += w >> 16;
        }
        #pragma unroll
        for (int off = 16; off > 0; off >>= 1) {
            lo += __shfl_down_sync(0xFFFFFFFFu, lo, off);
            hi += __shfl_down_sync(0xFFFFFFFFu, hi, off);
        }
        if (lane == 0) {
            gp[pbase + (2 * r) * MAXCHUNKS]     = lo;
            gp[pbase + (2 * r + 1) * MAXCHUNKS] = hi;
        }
    }
}

__global__ __launch_bounds__(1024)
void loss_kernel(float* __restrict__ out, float inv_denom) {
    __shared__ unsigned int wsum[32];
    const int t = threadIdx.x;
    const uint4* pf = g_part4;               // fake: one uint4 per bin
    const uint4* pr = g_part4 + ROWS * BINS; // real

    unsigned int s = 0;
    for (int bin = t; bin < ROWS * BINS; bin += 1024) {
        uint4 a = pf[bin];
        uint4 b = pr[bin];
        int f = (int)(a.x + a.y + a.z + a.w);
        int r = (int)(b.x + b.y + b.z + b.w);
        int d = f - r;
        s += (unsigned int)(d < 0 ? -d : d);
    }
    #pragma unroll
    for (int off = 16; off > 0; off >>= 1)
        s += __shfl_down_sync(0xFFFFFFFFu, s, off);
    if ((t & 31) == 0) wsum[t >> 5] = s;
    __syncthreads();
    if (t < 32) {
        unsigned int v = wsum[t];
        #pragma unroll
        for (int off = 16; off > 0; off >>= 1)
            v += __shfl_down_sync(0xFFFFFFFFu, v, off);
        if (t == 0) out[0] = (float)v * inv_denom;
    }
}

extern "C" void kernel_launch(void* const* d_in, const int* in_sizes, int n_in,
                              void* d_out, int out_size) {
    const float* fake = (const float*)d_in[0];
    const float* real = (const float*)d_in[1];
    const int total = in_sizes[0];          // 25165824
    const int hw = total / ROWS;            // 262144
    const int chunks = hw / EPB;            // 4

    dim3 grid((unsigned)(ROWS * chunks), 2);   // 768 blocks: single wave
    hist_kernel<<<grid, NTHREADS>>>(fake, real, hw, chunks);

    const float inv_denom = (float)(1.0 / ((double)ROWS * (double)BINS * (double)hw));
    loss_kernel<<<1, 1024>>>((float*)d_out, inv_denom);
}

// round 7
// speedup vs baseline: 1.0758x; 1.0758x over previous
#include <cuda_runtime.h>
#include <cuda_bf16.h>

// HistogramLoss: loss = mean |hist(fake) - hist(real)| over [B,C,BINS] rows,
// per-(b,c)-row normalized. Every clipped element lands in a bin, so each row
// sums to exactly H*W -> normalization is a constant scale; all counting is
// integer (bit-deterministic, stateless across graph replays).

#define ROWS 96               // B*C = 32*3
#define BINS 64
#define NTHREADS 256
#define EPB 32768             // elements per block (proven best config)
#define MAXCHUNKS 8           // hw / EPB = 262144 / 32768

// Per-block partials: [tensor(2)][row(96)][bin(64)][chunk(8)] u32.
// Every launch fully overwrites its slots -> no zeroing kernel, no state.
__device__ uint4 g_part4[(2 * ROWS * BINS * MAXCHUNKS) / 4];

// Grid-reduction state. Each replay adds then resets to 0 -> net stateless.
__device__ unsigned int g_acc = 0;
__device__ unsigned int g_ticket = 0;

__global__ __launch_bounds__(NTHREADS)
void hist_kernel(const float* __restrict__ fake,
                 const float* __restrict__ real,
                 int hw, int chunks) {
    // Per-thread privatized u16 counters, packed so bin-pair (2r,2r+1) for
    // thread t shares one 32-bit word:
    //   byte addr = ((bin & 62) << 9) + (t << 2) + ((bin & 1) << 1)
    // -> bank = t & 31 : strictly lane-dependent, ZERO conflicts for any data.
    __shared__ unsigned char s_raw[32 * NTHREADS * 4];   // 32 KB

    const int t = threadIdx.x;
    const int row = blockIdx.x / chunks;
    const int chunk = blockIdx.x - row * chunks;
    const int tensor = blockIdx.y;
    const float* __restrict__ src = tensor ? real : fake;

    // Zero the table (uint4 stores)
    uint4* sz = reinterpret_cast<uint4*>(s_raw);
    #pragma unroll
    for (int i = t; i < (32 * NTHREADS * 4) / 16; i += NTHREADS)
        sz[i] = make_uint4(0u, 0u, 0u, 0u);
    __syncthreads();

    const float4* __restrict__ p = reinterpret_cast<const float4*>(
        src + (size_t)row * (size_t)hw + (size_t)chunk * EPB);
    const int n4 = EPB / 4;                 // 8192
    const int t4 = t << 2;

    #pragma unroll 4
    for (int i = t; i < n4; i += NTHREADS) {
        float4 v = p[i];
        // torch.histc over [0,1]: clip, *BINS, trunc, clamp top bin.
        int b0 = min((int)(fminf(fmaxf(v.x, 0.0f), 1.0f) * 64.0f), 63);
        int b1 = min((int)(fminf(fmaxf(v.y, 0.0f), 1.0f) * 64.0f), 63);
        int b2 = min((int)(fminf(fmaxf(v.z, 0.0f), 1.0f) * 64.0f), 63);
        int b3 = min((int)(fminf(fmaxf(v.w, 0.0f), 1.0f) * 64.0f), 63);
        unsigned short* c0 = (unsigned short*)(s_raw + (((b0 & 62) << 9) + t4 + ((b0 & 1) << 1)));
        unsigned short* c1 = (unsigned short*)(s_raw + (((b1 & 62) << 9) + t4 + ((b1 & 1) << 1)));
        unsigned short* c2 = (unsigned short*)(s_raw + (((b2 & 62) << 9) + t4 + ((b2 & 1) << 1)));
        unsigned short* c3 = (unsigned short*)(s_raw + (((b3 & 62) << 9) + t4 + ((b3 & 1) << 1)));
        *c0 += 1; *c1 += 1; *c2 += 1; *c3 += 1;
    }
    __syncthreads();

    // Reduce 256 private copies -> 64 bins. Word-row r holds bins (2r, 2r+1).
    const unsigned int* sw = reinterpret_cast<const unsigned int*>(s_raw);
    const int warp = t >> 5;
    const int lane = t & 31;
    unsigned int* gp = reinterpret_cast<unsigned int*>(g_part4);
    const int pbase = ((tensor * ROWS + row) * BINS) * MAXCHUNKS + chunk;

    #pragma unroll
    for (int r = warp; r < 32; r += NTHREADS / 32) {
        unsigned int lo = 0, hi = 0;
        #pragma unroll
        for (int j = 0; j < NTHREADS / 32; ++j) {
            unsigned int w = sw[(r << 8) + lane + (j << 5)];
            lo += w & 0xFFFFu;
            hi += w >> 16;
        }
        #pragma unroll
        for (int off = 16; off > 0; off >>= 1) {
            lo += __shfl_down_sync(0xFFFFFFFFu, lo, off);
            hi += __shfl_down_sync(0xFFFFFFFFu, hi, off);
        }
        if (lane == 0) {
            gp[pbase + (2 * r) * MAXCHUNKS]     = lo;
            gp[pbase + (2 * r + 1) * MAXCHUNKS] = hi;
        }
    }
}

// 24 blocks x 256 threads: one bin per thread (6144 bins). Grid reduction via
// integer atomic + ticket; last block writes output and resets state so every
// graph replay starts from the same device state.
#define LOSS_BLOCKS 24
__global__ __launch_bounds__(NTHREADS)
void loss_kernel(float* __restrict__ out, float inv_denom) {
    __shared__ unsigned int wsum[NTHREADS / 32];
    const int t = threadIdx.x;
    const int bin = blockIdx.x * NTHREADS + t;     // 0 .. 6143

    const uint4* pf = g_part4;                                   // fake
    const uint4* pr = g_part4 + (ROWS * BINS * MAXCHUNKS) / 4;   // real
    uint4 a0 = pf[bin * 2], a1 = pf[bin * 2 + 1];
    uint4 b0 = pr[bin * 2], b1 = pr[bin * 2 + 1];
    int f = (int)(a0.x + a0.y + a0.z + a0.w + a1.x + a1.y + a1.z + a1.w);
    int r = (int)(b0.x + b0.y + b0.z + b0.w + b1.x + b1.y + b1.z + b1.w);
    int d = f - r;
    unsigned int s = (unsigned int)(d < 0 ? -d : d);

    #pragma unroll
    for (int off = 16; off > 0; off >>= 1)
        s += __shfl_down_sync(0xFFFFFFFFu, s, off);
    if ((t & 31) == 0) wsum[t >> 5] = s;
    __syncthreads();

    if (t == 0) {
        unsigned int v = 0;
        #pragma unroll
        for (int j = 0; j < NTHREADS / 32; ++j) v += wsum[j];
        atomicAdd(&g_acc, v);
        __threadfence();
        unsigned int done = atomicAdd(&g_ticket, 1u);
        if (done == LOSS_BLOCKS - 1) {
            unsigned int total = atomicAdd(&g_acc, 0u);   // all adds visible
            out[0] = (float)total * inv_denom;
            g_acc = 0u;        // reset for next graph replay
            g_ticket = 0u;
            __threadfence();
        }
    }
}

extern "C" void kernel_launch(void* const* d_in, const int* in_sizes, int n_in,
                              void* d_out, int out_size) {
    const float* fake = (const float*)d_in[0];
    const float* real = (const float*)d_in[1];
    const int total = in_sizes[0];          // 25165824
    const int hw = total / ROWS;            // 262144
    const int chunks = hw / EPB;            // 8

    dim3 grid((unsigned)(ROWS * chunks), 2);
    hist_kernel<<<grid, NTHREADS>>>(fake, real, hw, chunks);

    const float inv_denom = (float)(1.0 / ((double)ROWS * (double)BINS * (double)hw));
    loss_kernel<<<LOSS_BLOCKS, NTHREADS>>>((float*)d_out, inv_denom);
}